// round 12
// baseline (speedup 1.0000x reference)
#include <cuda_runtime.h>
#include <cstdint>

// DiscriminationLoss: B=16, C=4, H=W=640, labels in [0,16]
// loss = sum_b [ (sum over valid pairs i<j, i>=1 of log1p((3 - sqrt(m_i+m_j))^2)) / (nk*(nk-1)) ]
// m_k = SS_k / card_k^2.
//
// R11 vs R10 (41.4us; finalize 10.46us):
//  - SCRATCH TRANSPOSED to g_part[b][k][bx]: R10's finalize gather had lane
//    stride 136B -> ~32 L1tex wavefronts per LDG.64 -> ~17K wavefront-cycles
//    = the whole 10.5us. Coalesced layout cuts that ~16x.
//  - segment mainloop: #pragma unroll 2 for deeper LDG MLP (reg-budgeted by
//    __launch_bounds__(256,4)).

#define BATCH 16
#define CHAN 4
#define PIX (640 * 640)
#define NK 17            // labels 0..16
#define SIGMA_DIS 3.0f
#define GX 37            // blocks per batch (37*16 = 592 = 4/SM on 148 SMs)
#define NPAIR 120        // C(16,2) pairs with 1 <= i < j <= 16

// Packed pair table: entry t = (i << 5) | j, lexicographic (i,j), i<j.
__constant__ unsigned short c_pair[NPAIR] = {
    34,35,36,37,38,39,40,41,42,43,44,45,46,47,48,
    67,68,69,70,71,72,73,74,75,76,77,78,79,80,
    100,101,102,103,104,105,106,107,108,109,110,111,112,
    133,134,135,136,137,138,139,140,141,142,143,144,
    166,167,168,169,170,171,172,173,174,175,176,
    199,200,201,202,203,204,205,206,207,208,
    232,233,234,235,236,237,238,239,240,
    265,266,267,268,269,270,271,272,
    298,299,300,301,302,303,304,
    331,332,333,334,335,336,
    364,365,366,367,368,
    397,398,399,400,
    430,431,432,
    463,464,
    496
};

// Scratch (__device__ globals). Every element unconditionally overwritten
// each replay -> no init pass needed, graph-replay deterministic.
// Layout [b][k][bx]: bx innermost so finalize lanes (bx = lane) coalesce.
__device__ float2 g_part[BATCH][NK][GX];   // {ss, cnt}
__device__ int    g_part_max[BATCH][GX];

// ---------------------------------------------------------------------------
// Kernel 1: segment reduction (HBM-bound streaming pass).
// ---------------------------------------------------------------------------
__global__ __launch_bounds__(256, 4)
void segment_reduce_kernel(const float* __restrict__ pred,
                           const int*  __restrict__ labels) {
    __shared__ float2 s_bin[NK][256];   // 34.8 KB; [bin][tid]: LDS.64 two-
                                        // phase, conflict-free
    __shared__ int s_max;

    const int tid = threadIdx.x;
    const int bx  = blockIdx.x;
    const int b   = blockIdx.y;

    #pragma unroll
    for (int k = 0; k < NK; k++) s_bin[k][tid] = make_float2(0.0f, 0.0f);
    if (tid == 0) s_max = 0;
    __syncthreads();

    const float* p0 = pred + (size_t)b * CHAN * PIX;
    const int*   l0 = labels + (size_t)b * PIX;

    const float4* c0 = (const float4*)(p0);
    const float4* c1 = (const float4*)(p0 + PIX);
    const float4* c2 = (const float4*)(p0 + 2 * PIX);
    const float4* c3 = (const float4*)(p0 + 3 * PIX);
    const int4*   lv4 = (const int4*)(l0);

    int maxl = 0;
    const int n4     = PIX / 4;          // 102400
    const int stride = GX * 256;

    #pragma unroll 2
    for (int i = bx * 256 + tid; i < n4; i += stride) {
        float4 x0 = c0[i];
        float4 x1 = c1[i];
        float4 x2 = c2[i];
        float4 x3 = c3[i];
        int4   lv = lv4[i];

        float sq0 = x0.x * x0.x + x1.x * x1.x + x2.x * x2.x + x3.x * x3.x;
        float sq1 = x0.y * x0.y + x1.y * x1.y + x2.y * x2.y + x3.y * x3.y;
        float sq2 = x0.z * x0.z + x1.z * x1.z + x2.z * x2.z + x3.z * x3.z;
        float sq3 = x0.w * x0.w + x1.w * x1.w + x2.w * x2.w + x3.w * x3.w;

        int la = min(max(lv.x, 0), NK - 1);
        int lb = min(max(lv.y, 0), NK - 1);
        int lc = min(max(lv.z, 0), NK - 1);
        int ld = min(max(lv.w, 0), NK - 1);

        // per-thread private bins: sequential RMW, no races, no conflicts
        float2 v;
        v = s_bin[la][tid]; v.x += sq0; v.y += 1.0f; s_bin[la][tid] = v;
        v = s_bin[lb][tid]; v.x += sq1; v.y += 1.0f; s_bin[lb][tid] = v;
        v = s_bin[lc][tid]; v.x += sq2; v.y += 1.0f; s_bin[lc][tid] = v;
        v = s_bin[ld][tid]; v.x += sq3; v.y += 1.0f; s_bin[ld][tid] = v;

        maxl = max(maxl, max(max(la, lb), max(lc, ld)));
    }

    #pragma unroll
    for (int o = 16; o > 0; o >>= 1)
        maxl = max(maxl, __shfl_xor_sync(0xFFFFFFFFu, maxl, o));
    if ((tid & 31) == 0) atomicMax(&s_max, maxl);

    __syncthreads();

    // block tree-reduce the 256 private columns per bin
    for (int s = 128; s >= 1; s >>= 1) {
        if (tid < s) {
            #pragma unroll
            for (int k = 0; k < NK; k++) {
                float2 a = s_bin[k][tid];
                float2 c = s_bin[k][tid + s];
                a.x += c.x; a.y += c.y;
                s_bin[k][tid] = a;
            }
        }
        __syncthreads();
    }

    // plain stores to this block's private scratch slots (no atomics)
    if (tid < NK) g_part[b][tid][bx] = s_bin[tid][0];
    if (tid == 0) g_part_max[b][bx] = s_max;
}

// ---------------------------------------------------------------------------
// Kernel 2: finalize. 1 block, 16 warps; warp w = batch w.
// Gather is coalesced: per k, lanes read consecutive bx slots.
// ---------------------------------------------------------------------------
__global__ __launch_bounds__(512, 1)
void finalize_kernel(float* __restrict__ out) {
    __shared__ float s_loss[BATCH];

    const int lane = threadIdx.x & 31;
    const int b    = threadIdx.x >> 5;

    float ss[NK], cnt[NK];
    int maxl = 0;

    // first slice: bx = lane (lane >= GX contributes zero)
    #pragma unroll
    for (int k = 0; k < NK; k++) {
        float2 v = (lane < GX) ? g_part[b][k][lane] : make_float2(0.0f, 0.0f);
        ss[k] = v.x;  cnt[k] = v.y;
    }
    if (lane < GX) maxl = g_part_max[b][lane];
    // second slice: bx = lane + 32 (only lanes 0..GX-33)
    if (lane + 32 < GX) {
        #pragma unroll
        for (int k = 0; k < NK; k++) {
            float2 v = g_part[b][k][lane + 32];
            ss[k]  += v.x;
            cnt[k] += v.y;
        }
        maxl = max(maxl, g_part_max[b][lane + 32]);
    }

    // full butterfly: every lane ends with the batch totals
    #pragma unroll
    for (int o = 16; o > 0; o >>= 1) {
        #pragma unroll
        for (int k = 0; k < NK; k++) {
            ss[k]  += __shfl_xor_sync(0xFFFFFFFFu, ss[k],  o);
            cnt[k] += __shfl_xor_sync(0xFFFFFFFFu, cnt[k], o);
        }
        maxl = max(maxl, __shfl_xor_sync(0xFFFFFFFFu, maxl, o));
    }

    float m[NK];
    #pragma unroll
    for (int k = 0; k < NK; k++)
        m[k] = (cnt[k] > 0.0f) ? ss[k] / (cnt[k] * cnt[k]) : 0.0f;

    // pair terms split across lanes: lane p takes t = p, p+32, p+64, p+96.
    float ps = 0.0f;
    #pragma unroll
    for (int t = lane; t < NPAIR; t += 32) {
        int pk = (int)c_pair[t];
        int i = pk >> 5;
        int j = pk & 31;
        if (cnt[i] > 0.0f && cnt[j] > 0.0f) {
            float d = sqrtf(m[i] + m[j]);
            float u = SIGMA_DIS - d;
            ps += log1pf(u * u);
        }
    }
    #pragma unroll
    for (int o = 16; o > 0; o >>= 1)
        ps += __shfl_xor_sync(0xFFFFFFFFu, ps, o);

    if (lane == 0) {
        float loss = 0.0f;
        if (maxl > 1) {
            float denom = (float)(maxl * (maxl - 1));
            loss = ps / fmaxf(denom, 1.0f);
        }
        s_loss[b] = loss;
    }
    __syncthreads();

    if (threadIdx.x == 0) {
        float s = 0.0f;
        #pragma unroll
        for (int k = 0; k < BATCH; k++) s += s_loss[k];
        out[0] = s;
    }
}

// ---------------------------------------------------------------------------
extern "C" void kernel_launch(void* const* d_in, const int* in_sizes, int n_in,
                              void* d_out, int out_size) {
    const float* pred   = (const float*)d_in[0];   // (16,4,640,640) f32
    const int*   labels = (const int*)d_in[1];     // (16,640,640) i32
    float*       out    = (float*)d_out;

    dim3 grid(GX, BATCH);   // 592 blocks = 4/SM on 148 SMs, one wave
    segment_reduce_kernel<<<grid, 256>>>(pred, labels);

    finalize_kernel<<<1, 512>>>(out);
}